// round 11
// baseline (speedup 1.0000x reference)
#include <cuda_runtime.h>
#include <cstdint>

// Modulated deformable conv 3x3, in_ch=out_ch=1, stride=1, pad=1, dil=1.
// H=W=512, B<=8 hardcoded. R11: two kernels.
//  1) prep: g_tile[b][y][xx] = {d[y][xx-1]|0, d[y][xx]|0}, xx in [0,512]
//  2) main: R10 skeleton (2 rows/thread vertical gathers, warp-cooperative
//     cp.async staging, NS=3) but each bilinear corner-pair is ONE LDG.64
//     from the tile -> half the gather instructions, no x-OOB predicates.

#define Hc 512
#define Wc 512
#define HWc (Hc * Wc)
#define TW 513                    // tile entries per row
#define THWc (Hc * TW)            // tile entries per image
#define NS 3                      // pipeline stages
#define SLAB_FLOATS 192           // dy[64] dx[64] m[64] per warp per stage
#define STAGE_BYTES (8 * SLAB_FLOATS * 4)

__device__ __align__(16) float2 g_tile[8 * THWc];   // 16.8 MB scratch

__device__ __forceinline__ uint32_t smem_u32(const void* p) {
    uint32_t a;
    asm("{ .reg .u64 t; cvta.to.shared.u64 t, %1; cvt.u32.u64 %0, t; }"
        : "=r"(a) : "l"(p));
    return a;
}

#define CP_ASYNC_16(dst, src) \
    asm volatile("cp.async.cg.shared.global [%0], [%1], 16;" \
                 :: "r"(dst), "l"(src) : "memory")
#define CP_COMMIT() asm volatile("cp.async.commit_group;" ::: "memory")
#define CP_WAIT(n)  asm volatile("cp.async.wait_group %0;" :: "n"(n) : "memory")

// ---- kernel 1: build horizontally-paired depth tile --------------------
__global__ __launch_bounds__(256)
void prep_kernel(const float* __restrict__ depth, int total)
{
    int i = blockIdx.x * blockDim.x + threadIdx.x;
    if (i >= total) return;
    int xx   = i % TW;            // 0..512
    int rest = i / TW;
    int y    = rest & 511;
    int b    = rest >> 9;
    const float* row = depth + (size_t)b * HWc + (y << 9);
    float l = (xx >= 1)   ? __ldg(row + xx - 1) : 0.0f;
    float r = (xx <= 511) ? __ldg(row + xx)     : 0.0f;
    g_tile[i] = make_float2(l, r);
}

// ---- bilinear from paired tile: 2 predicated LDG.64 --------------------
__device__ __forceinline__ float bilin_tile(const float2* __restrict__ tb,
                                            float y, float x) {
    float y0f = floorf(y);
    float x0f = floorf(x);
    float wy = y - y0f;
    float wx = x - x0f;
    int y0  = (int)y0f;
    int txx = (int)x0f + 1;               // tile x index
    bool vx  = (unsigned)txx <= 512u;
    bool vy0 = vx && ((unsigned)y0       < (unsigned)Hc);
    bool vy1 = vx && ((unsigned)(y0 + 1) < (unsigned)Hc);
    const float2* p = tb + y0 * TW + txx;
    float2 a = vy0 ? __ldg(p)      : make_float2(0.0f, 0.0f);
    float2 c = vy1 ? __ldg(p + TW) : make_float2(0.0f, 0.0f);
    float top = fmaf(wx, a.y - a.x, a.x);
    float bot = fmaf(wx, c.y - c.x, c.x);
    return fmaf(wy, bot - top, top);
}

// ---- kernel 2: main DCN ------------------------------------------------
__global__ __launch_bounds__(256, 8)
void dcn_kernel(const float* __restrict__ mask,
                const float* __restrict__ off,
                const float* __restrict__ w9,
                const float* __restrict__ bias,
                float* __restrict__ out,
                int B)
{
    __shared__ __align__(16) float slab[NS][8][SLAB_FLOATS];

    int tid  = threadIdx.x;
    int lane = tid & 31;
    int wrp  = tid >> 5;
    int bid  = blockIdx.x;
    int b    = bid >> 9;          // 512 blocks per image
    int rem  = bid & 511;
    int ys   = rem >> 1;          // 256 y-strips of 2 rows
    int xs   = rem & 1;           // 2 x-strips of 256 px
    int y0   = ys << 1;
    int xw   = (xs << 8) + (wrp << 5);
    int x    = xw + lane;

    const float2* tb   = g_tile + (size_t)b * THWc;
    const float* obase = off   + (size_t)b * 18 * HWc + (y0 << 9) + xw;
    const float* mbase = mask  + (size_t)b * 9  * HWc + (y0 << 9) + xw;

    // Cooperative copy mapping (see R8-R10):
    int arr  = lane >> 4;
    int cc   = lane & 15;
    int coff = ((cc >> 3) << 9) + ((cc & 7) << 2);
    int moff = ((lane >> 3) << 9) + ((lane & 7) << 2);

    uint32_t warp_base = smem_u32(&slab[0][wrp][0]);
    uint32_t adst0 = warp_base + (uint32_t)lane * 16;
    uint32_t bdst0 = warp_base + 512 + (uint32_t)lane * 16;

    #pragma unroll
    for (int t = 0; t < NS; t++) {
        CP_ASYNC_16(adst0 + t * STAGE_BYTES, obase + (size_t)(2 * t + arr) * HWc + coff);
        if (lane < 16)
            CP_ASYNC_16(bdst0 + t * STAGE_BYTES, mbase + (size_t)t * HWc + moff);
        CP_COMMIT();
    }

    float acc0 = 0.0f, acc1 = 0.0f;
    float xf = (float)x;

    #pragma unroll
    for (int t = 0; t < 9; t++) {
        const int s = t % NS;

        CP_WAIT(NS - 1);
        __syncwarp();

        const float* f = &slab[s][wrp][0];
        float dy0 = f[lane],       dy1 = f[32 + lane];
        float dx0 = f[64 + lane],  dx1 = f[96 + lane];
        float m0  = f[128 + lane], m1  = f[160 + lane];

        int tn = t + NS;
        if (tn < 9) {
            CP_ASYNC_16(adst0 + s * STAGE_BYTES, obase + (size_t)(2 * tn + arr) * HWc + coff);
            if (lane < 16)
                CP_ASYNC_16(bdst0 + s * STAGE_BYTES, mbase + (size_t)tn * HWc + moff);
        }
        CP_COMMIT();

        float wt = __ldg(w9 + t);
        float ybase = (float)(y0 - 1 + t / 3);
        float xtap  = xf + (float)(t % 3 - 1);

        float sv;
        sv = bilin_tile(tb, ybase + 0.0f + dy0, xtap + dx0);
        acc0 = fmaf(sv, m0 * wt, acc0);
        sv = bilin_tile(tb, ybase + 1.0f + dy1, xtap + dx1);
        acc1 = fmaf(sv, m1 * wt, acc1);
    }

    float bv = __ldg(bias);
    float* optr = out + (size_t)b * HWc + (y0 << 9) + x;
    optr[0]  = acc0 + bv;
    optr[Wc] = acc1 + bv;
}

extern "C" void kernel_launch(void* const* d_in, const int* in_sizes, int n_in,
                              void* d_out, int out_size)
{
    const float* depth = (const float*)d_in[0];
    const float* mask  = (const float*)d_in[1];
    const float* off   = (const float*)d_in[2];
    const float* w9    = (const float*)d_in[3];
    const float* bias  = (const float*)d_in[4];
    float* out = (float*)d_out;

    int B = in_sizes[0] / HWc;

    int total = B * THWc;
    prep_kernel<<<(total + 255) / 256, 256>>>(depth, total);

    int blocks = B * 512;
    dcn_kernel<<<blocks, 256>>>(mask, off, w9, bias, out, B);
}

// round 12
// speedup vs baseline: 1.2222x; 1.2222x over previous
#include <cuda_runtime.h>
#include <cuda_fp16.h>
#include <cstdint>

// Modulated deformable conv 3x3, in_ch=out_ch=1, stride=1, pad=1, dil=1.
// H=W=512, B<=8. R12: R10 skeleton + fp16x2 horizontally-paired depth tile.
//  prep: g_pair[b][y][xx] = half2{d[y][xx-1]|0, d[y][xx]|0}, xx in [0,512]
//        -> 4B/entry, SAME gather footprint as raw depth (8.4MB), unlike
//        the failed R11 float2 tile (16.8MB).
//  main: each bilinear corner-pair = ONE predicated 4B LDG + h2->f2 cvt.
//        Gather LDG count halved, x-OOB predicates eliminated.

#define Hc 512
#define Wc 512
#define HWc (Hc * Wc)
#define TW 513                    // tile entries per row
#define THWc (Hc * TW)
#define NS 3                      // pipeline stages
#define SLAB_FLOATS 192           // dy[64] dx[64] m[64] per warp per stage
#define STAGE_BYTES (8 * SLAB_FLOATS * 4)

__device__ __align__(16) __half2 g_pair[8 * THWc];   // 8.4 MB scratch

__device__ __forceinline__ uint32_t smem_u32(const void* p) {
    uint32_t a;
    asm("{ .reg .u64 t; cvta.to.shared.u64 t, %1; cvt.u32.u64 %0, t; }"
        : "=r"(a) : "l"(p));
    return a;
}

#define CP_ASYNC_16(dst, src) \
    asm volatile("cp.async.cg.shared.global [%0], [%1], 16;" \
                 :: "r"(dst), "l"(src) : "memory")
#define CP_COMMIT() asm volatile("cp.async.commit_group;" ::: "memory")
#define CP_WAIT(n)  asm volatile("cp.async.wait_group %0;" :: "n"(n) : "memory")

// ---- kernel 1: build fp16 paired depth tile -----------------------------
__global__ __launch_bounds__(256)
void prep_kernel(const float* __restrict__ depth, int total)
{
    int i = blockIdx.x * blockDim.x + threadIdx.x;
    if (i >= total) return;
    int xx   = i % TW;            // 0..512
    int rest = i / TW;
    int y    = rest & 511;
    int b    = rest >> 9;
    const float* row = depth + (size_t)b * HWc + (y << 9);
    float l = (xx >= 1)   ? __ldg(row + xx - 1) : 0.0f;
    float r = (xx <= 511) ? __ldg(row + xx)     : 0.0f;
    g_pair[i] = __floats2half2_rn(l, r);
}

// ---- bilinear from fp16 paired tile: 2 predicated 4B LDGs ---------------
__device__ __forceinline__ float bilin_pair(const __half2* __restrict__ tb,
                                            float y, float x) {
    float y0f = floorf(y);
    float x0f = floorf(x);
    float wy = y - y0f;
    float wx = x - x0f;
    int y0  = (int)y0f;
    int txx = (int)x0f + 1;                 // tile x index, valid [0,512]
    bool vx  = (unsigned)txx <= 512u;
    bool vy0 = vx && ((unsigned)y0       < (unsigned)Hc);
    bool vy1 = vx && ((unsigned)(y0 + 1) < (unsigned)Hc);
    const __half2* p = tb + y0 * TW + txx;
    __half2 z = __half2half2(__float2half(0.0f));
    __half2 a = vy0 ? __ldg(p)      : z;
    __half2 c = vy1 ? __ldg(p + TW) : z;
    float2 af = __half22float2(a);
    float2 cf = __half22float2(c);
    float top = fmaf(wx, af.y - af.x, af.x);
    float bot = fmaf(wx, cf.y - cf.x, cf.x);
    return fmaf(wy, bot - top, top);
}

// ---- kernel 2: main DCN --------------------------------------------------
__global__ __launch_bounds__(256, 8)
void dcn_kernel(const float* __restrict__ mask,
                const float* __restrict__ off,
                const float* __restrict__ w9,
                const float* __restrict__ bias,
                float* __restrict__ out,
                int B)
{
    __shared__ __align__(16) float slab[NS][8][SLAB_FLOATS];

    int tid  = threadIdx.x;
    int lane = tid & 31;
    int wrp  = tid >> 5;
    int bid  = blockIdx.x;
    int b    = bid >> 9;          // 512 blocks per image
    int rem  = bid & 511;
    int ys   = rem >> 1;          // 256 y-strips of 2 rows
    int xs   = rem & 1;           // 2 x-strips of 256 px
    int y0   = ys << 1;
    int xw   = (xs << 8) + (wrp << 5);
    int x    = xw + lane;

    const __half2* tb  = g_pair + (size_t)b * THWc;
    const float* obase = off  + (size_t)b * 18 * HWc + (y0 << 9) + xw;
    const float* mbase = mask + (size_t)b * 9  * HWc + (y0 << 9) + xw;

    // Cooperative copy mapping (see R8-R10)
    int arr  = lane >> 4;
    int cc   = lane & 15;
    int coff = ((cc >> 3) << 9) + ((cc & 7) << 2);
    int moff = ((lane >> 3) << 9) + ((lane & 7) << 2);

    uint32_t warp_base = smem_u32(&slab[0][wrp][0]);
    uint32_t adst0 = warp_base + (uint32_t)lane * 16;
    uint32_t bdst0 = warp_base + 512 + (uint32_t)lane * 16;

    #pragma unroll
    for (int t = 0; t < NS; t++) {
        CP_ASYNC_16(adst0 + t * STAGE_BYTES, obase + (size_t)(2 * t + arr) * HWc + coff);
        if (lane < 16)
            CP_ASYNC_16(bdst0 + t * STAGE_BYTES, mbase + (size_t)t * HWc + moff);
        CP_COMMIT();
    }

    float acc0 = 0.0f, acc1 = 0.0f;
    float xf = (float)x;

    #pragma unroll
    for (int t = 0; t < 9; t++) {
        const int s = t % NS;

        CP_WAIT(NS - 1);
        __syncwarp();

        const float* f = &slab[s][wrp][0];
        float dy0 = f[lane],       dy1 = f[32 + lane];
        float dx0 = f[64 + lane],  dx1 = f[96 + lane];
        float m0  = f[128 + lane], m1  = f[160 + lane];

        int tn = t + NS;
        if (tn < 9) {
            CP_ASYNC_16(adst0 + s * STAGE_BYTES, obase + (size_t)(2 * tn + arr) * HWc + coff);
            if (lane < 16)
                CP_ASYNC_16(bdst0 + s * STAGE_BYTES, mbase + (size_t)tn * HWc + moff);
        }
        CP_COMMIT();

        float wt = __ldg(w9 + t);
        float ybase = (float)(y0 - 1 + t / 3);
        float xtap  = xf + (float)(t % 3 - 1);

        float sv;
        sv = bilin_pair(tb, ybase + 0.0f + dy0, xtap + dx0);
        acc0 = fmaf(sv, m0 * wt, acc0);
        sv = bilin_pair(tb, ybase + 1.0f + dy1, xtap + dx1);
        acc1 = fmaf(sv, m1 * wt, acc1);
    }

    float bv = __ldg(bias);
    float* optr = out + (size_t)b * HWc + (y0 << 9) + x;
    optr[0]  = acc0 + bv;
    optr[Wc] = acc1 + bv;
}

extern "C" void kernel_launch(void* const* d_in, const int* in_sizes, int n_in,
                              void* d_out, int out_size)
{
    const float* depth = (const float*)d_in[0];
    const float* mask  = (const float*)d_in[1];
    const float* off   = (const float*)d_in[2];
    const float* w9    = (const float*)d_in[3];
    const float* bias  = (const float*)d_in[4];
    float* out = (float*)d_out;

    int B = in_sizes[0] / HWc;

    int total = B * THWc;
    prep_kernel<<<(total + 255) / 256, 256>>>(depth, total);

    int blocks = B * 512;
    dcn_kernel<<<blocks, 256>>>(mask, off, w9, bias, out, B);
}

// round 13
// speedup vs baseline: 1.2862x; 1.0524x over previous
#include <cuda_runtime.h>
#include <cuda_fp16.h>
#include <cstdint>

// Modulated deformable conv 3x3, in_ch=out_ch=1, stride=1, pad=1, dil=1.
// H=W=512, B<=8. R13: R12 main kernel (fp16x2 paired-depth gathers, halved
// gather LDGs) + vectorized prep (block-per-row, float4 in, uint4 out,
// zero integer division). TW padded 513->516 for 16B-aligned stores.

#define Hc 512
#define Wc 512
#define HWc (Hc * Wc)
#define TW 516                    // padded tile entries per row (513 used)
#define THWc (Hc * TW)
#define NS 3                      // pipeline stages
#define SLAB_FLOATS 192           // dy[64] dx[64] m[64] per warp per stage
#define STAGE_BYTES (8 * SLAB_FLOATS * 4)

__device__ __align__(16) __half2 g_pair[8 * THWc];   // 8.5 MB scratch

__device__ __forceinline__ uint32_t smem_u32(const void* p) {
    uint32_t a;
    asm("{ .reg .u64 t; cvta.to.shared.u64 t, %1; cvt.u32.u64 %0, t; }"
        : "=r"(a) : "l"(p));
    return a;
}

#define CP_ASYNC_16(dst, src) \
    asm volatile("cp.async.cg.shared.global [%0], [%1], 16;" \
                 :: "r"(dst), "l"(src) : "memory")
#define CP_COMMIT() asm volatile("cp.async.commit_group;" ::: "memory")
#define CP_WAIT(n)  asm volatile("cp.async.wait_group %0;" :: "n"(n) : "memory")

// ---- kernel 1: build fp16 paired depth tile (vectorized) ----------------
// Block = one image row. Thread t (t<129) covers tile entries 4t..4t+3:
//   entry e = {fp16(d[e-1]|0), fp16(d[e]|0)},  e valid in [0,512].
__global__ __launch_bounds__(160)
void prep_kernel(const float* __restrict__ depth)
{
    int t = threadIdx.x;
    if (t >= 129) return;
    int y = blockIdx.x & 511;
    int b = blockIdx.x >> 9;
    const float* row = depth + (size_t)b * HWc + (y << 9);

    int e0 = t << 2;                       // 0,4,...,512
    float4 v;
    if (e0 <= 508) v = *(const float4*)(row + e0);       // d[e0..e0+3]
    else           v = make_float4(0.f, 0.f, 0.f, 0.f);  // e0=512: OOB
    float lm = (e0 > 0) ? __ldg(row + e0 - 1) : 0.0f;    // d[e0-1]

    __half2 h0 = __floats2half2_rn(lm,  v.x);
    __half2 h1 = __floats2half2_rn(v.x, v.y);
    __half2 h2 = __floats2half2_rn(v.y, v.z);
    __half2 h3 = __floats2half2_rn(v.z, v.w);

    __half2* dst = g_pair + (size_t)b * THWc + y * TW + e0;
    uint4 pack;
    pack.x = *(uint32_t*)&h0;
    pack.y = *(uint32_t*)&h1;
    pack.z = *(uint32_t*)&h2;
    pack.w = *(uint32_t*)&h3;
    *(uint4*)dst = pack;
}

// ---- bilinear from fp16 paired tile: 2 predicated 4B LDGs ---------------
__device__ __forceinline__ float bilin_pair(const __half2* __restrict__ tb,
                                            float y, float x) {
    float y0f = floorf(y);
    float x0f = floorf(x);
    float wy = y - y0f;
    float wx = x - x0f;
    int y0  = (int)y0f;
    int txx = (int)x0f + 1;                 // tile x index, valid [0,512]
    bool vx  = (unsigned)txx <= 512u;
    bool vy0 = vx && ((unsigned)y0       < (unsigned)Hc);
    bool vy1 = vx && ((unsigned)(y0 + 1) < (unsigned)Hc);
    const __half2* p = tb + y0 * TW + txx;
    __half2 z = __half2half2(__float2half(0.0f));
    __half2 a = vy0 ? __ldg(p)      : z;
    __half2 c = vy1 ? __ldg(p + TW) : z;
    float2 af = __half22float2(a);
    float2 cf = __half22float2(c);
    float top = fmaf(wx, af.y - af.x, af.x);
    float bot = fmaf(wx, cf.y - cf.x, cf.x);
    return fmaf(wy, bot - top, top);
}

// ---- kernel 2: main DCN --------------------------------------------------
__global__ __launch_bounds__(256, 8)
void dcn_kernel(const float* __restrict__ mask,
                const float* __restrict__ off,
                const float* __restrict__ w9,
                const float* __restrict__ bias,
                float* __restrict__ out,
                int B)
{
    __shared__ __align__(16) float slab[NS][8][SLAB_FLOATS];

    int tid  = threadIdx.x;
    int lane = tid & 31;
    int wrp  = tid >> 5;
    int bid  = blockIdx.x;
    int b    = bid >> 9;          // 512 blocks per image
    int rem  = bid & 511;
    int ys   = rem >> 1;          // 256 y-strips of 2 rows
    int xs   = rem & 1;           // 2 x-strips of 256 px
    int y0   = ys << 1;
    int xw   = (xs << 8) + (wrp << 5);
    int x    = xw + lane;

    const __half2* tb  = g_pair + (size_t)b * THWc;
    const float* obase = off  + (size_t)b * 18 * HWc + (y0 << 9) + xw;
    const float* mbase = mask + (size_t)b * 9  * HWc + (y0 << 9) + xw;

    // Cooperative copy mapping (see R8-R10)
    int arr  = lane >> 4;
    int cc   = lane & 15;
    int coff = ((cc >> 3) << 9) + ((cc & 7) << 2);
    int moff = ((lane >> 3) << 9) + ((lane & 7) << 2);

    uint32_t warp_base = smem_u32(&slab[0][wrp][0]);
    uint32_t adst0 = warp_base + (uint32_t)lane * 16;
    uint32_t bdst0 = warp_base + 512 + (uint32_t)lane * 16;

    #pragma unroll
    for (int t = 0; t < NS; t++) {
        CP_ASYNC_16(adst0 + t * STAGE_BYTES, obase + (size_t)(2 * t + arr) * HWc + coff);
        if (lane < 16)
            CP_ASYNC_16(bdst0 + t * STAGE_BYTES, mbase + (size_t)t * HWc + moff);
        CP_COMMIT();
    }

    float acc0 = 0.0f, acc1 = 0.0f;
    float xf = (float)x;

    #pragma unroll
    for (int t = 0; t < 9; t++) {
        const int s = t % NS;

        CP_WAIT(NS - 1);
        __syncwarp();

        const float* f = &slab[s][wrp][0];
        float dy0 = f[lane],       dy1 = f[32 + lane];
        float dx0 = f[64 + lane],  dx1 = f[96 + lane];
        float m0  = f[128 + lane], m1  = f[160 + lane];

        int tn = t + NS;
        if (tn < 9) {
            CP_ASYNC_16(adst0 + s * STAGE_BYTES, obase + (size_t)(2 * tn + arr) * HWc + coff);
            if (lane < 16)
                CP_ASYNC_16(bdst0 + s * STAGE_BYTES, mbase + (size_t)tn * HWc + moff);
        }
        CP_COMMIT();

        float wt = __ldg(w9 + t);
        float ybase = (float)(y0 - 1 + t / 3);
        float xtap  = xf + (float)(t % 3 - 1);

        float sv;
        sv = bilin_pair(tb, ybase + 0.0f + dy0, xtap + dx0);
        acc0 = fmaf(sv, m0 * wt, acc0);
        sv = bilin_pair(tb, ybase + 1.0f + dy1, xtap + dx1);
        acc1 = fmaf(sv, m1 * wt, acc1);
    }

    float bv = __ldg(bias);
    float* optr = out + (size_t)b * HWc + (y0 << 9) + x;
    optr[0]  = acc0 + bv;
    optr[Wc] = acc1 + bv;
}

extern "C" void kernel_launch(void* const* d_in, const int* in_sizes, int n_in,
                              void* d_out, int out_size)
{
    const float* depth = (const float*)d_in[0];
    const float* mask  = (const float*)d_in[1];
    const float* off   = (const float*)d_in[2];
    const float* w9    = (const float*)d_in[3];
    const float* bias  = (const float*)d_in[4];
    float* out = (float*)d_out;

    int B = in_sizes[0] / HWc;

    prep_kernel<<<B * 512, 160>>>(depth);

    int blocks = B * 512;
    dcn_kernel<<<blocks, 256>>>(mask, off, w9, bias, out, B);
}

// round 14
// speedup vs baseline: 1.2886x; 1.0019x over previous
#include <cuda_runtime.h>
#include <cuda_fp16.h>
#include <cstdint>

// Modulated deformable conv 3x3, in_ch=out_ch=1, stride=1, pad=1, dil=1.
// H=W=512, B<=8. R14: R13 with dead-lane-free prep (128 thr/block, one
// float4->uint4 per thread, lane 127 writes the tail entry) and streaming
// (evict-first) output stores in the main kernel.

#define Hc 512
#define Wc 512
#define HWc (Hc * Wc)
#define TW 516                    // padded tile entries per row (513 used)
#define THWc (Hc * TW)
#define NS 3                      // pipeline stages
#define SLAB_FLOATS 192           // dy[64] dx[64] m[64] per warp per stage
#define STAGE_BYTES (8 * SLAB_FLOATS * 4)

__device__ __align__(16) __half2 g_pair[8 * THWc];   // 8.5 MB scratch

__device__ __forceinline__ uint32_t smem_u32(const void* p) {
    uint32_t a;
    asm("{ .reg .u64 t; cvta.to.shared.u64 t, %1; cvt.u32.u64 %0, t; }"
        : "=r"(a) : "l"(p));
    return a;
}

#define CP_ASYNC_16(dst, src) \
    asm volatile("cp.async.cg.shared.global [%0], [%1], 16;" \
                 :: "r"(dst), "l"(src) : "memory")
#define CP_COMMIT() asm volatile("cp.async.commit_group;" ::: "memory")
#define CP_WAIT(n)  asm volatile("cp.async.wait_group %0;" :: "n"(n) : "memory")

// ---- kernel 1: build fp16 paired depth tile -----------------------------
// Block = one image row, 128 threads (4 full warps, zero dead lanes).
// Thread t covers tile entries [4t, 4t+4): one float4 load, one uint4 store.
// Entry e = {fp16(d[e-1]|0), fp16(d[e]|0)}. Lane 127 also writes entry 512.
__global__ __launch_bounds__(128)
void prep_kernel(const float* __restrict__ depth)
{
    int t = threadIdx.x;               // 0..127
    int y = blockIdx.x & 511;
    int b = blockIdx.x >> 9;
    const float* row = depth + (size_t)b * HWc + (y << 9);

    int e0 = t << 2;                   // 0,4,...,508
    float4 v = *(const float4*)(row + e0);            // d[e0..e0+3]
    float lm = (e0 > 0) ? __ldg(row + e0 - 1) : 0.0f; // d[e0-1]

    __half2 h0 = __floats2half2_rn(lm,  v.x);
    __half2 h1 = __floats2half2_rn(v.x, v.y);
    __half2 h2 = __floats2half2_rn(v.y, v.z);
    __half2 h3 = __floats2half2_rn(v.z, v.w);

    __half2* dst = g_pair + (size_t)b * THWc + y * TW + e0;
    uint4 pack;
    pack.x = *(uint32_t*)&h0;
    pack.y = *(uint32_t*)&h1;
    pack.z = *(uint32_t*)&h2;
    pack.w = *(uint32_t*)&h3;
    *(uint4*)dst = pack;

    if (t == 127) {                    // entry 512 = {d[511], 0}
        dst[4] = __floats2half2_rn(v.w, 0.0f);
    }
}

// ---- bilinear from fp16 paired tile: 2 predicated 4B LDGs ---------------
__device__ __forceinline__ float bilin_pair(const __half2* __restrict__ tb,
                                            float y, float x) {
    float y0f = floorf(y);
    float x0f = floorf(x);
    float wy = y - y0f;
    float wx = x - x0f;
    int y0  = (int)y0f;
    int txx = (int)x0f + 1;                 // tile x index, valid [0,512]
    bool vx  = (unsigned)txx <= 512u;
    bool vy0 = vx && ((unsigned)y0       < (unsigned)Hc);
    bool vy1 = vx && ((unsigned)(y0 + 1) < (unsigned)Hc);
    const __half2* p = tb + y0 * TW + txx;
    __half2 z = __half2half2(__float2half(0.0f));
    __half2 a = vy0 ? __ldg(p)      : z;
    __half2 c = vy1 ? __ldg(p + TW) : z;
    float2 af = __half22float2(a);
    float2 cf = __half22float2(c);
    float top = fmaf(wx, af.y - af.x, af.x);
    float bot = fmaf(wx, cf.y - cf.x, cf.x);
    return fmaf(wy, bot - top, top);
}

// ---- kernel 2: main DCN --------------------------------------------------
__global__ __launch_bounds__(256, 8)
void dcn_kernel(const float* __restrict__ mask,
                const float* __restrict__ off,
                const float* __restrict__ w9,
                const float* __restrict__ bias,
                float* __restrict__ out,
                int B)
{
    __shared__ __align__(16) float slab[NS][8][SLAB_FLOATS];

    int tid  = threadIdx.x;
    int lane = tid & 31;
    int wrp  = tid >> 5;
    int bid  = blockIdx.x;
    int b    = bid >> 9;          // 512 blocks per image
    int rem  = bid & 511;
    int ys   = rem >> 1;          // 256 y-strips of 2 rows
    int xs   = rem & 1;           // 2 x-strips of 256 px
    int y0   = ys << 1;
    int xw   = (xs << 8) + (wrp << 5);
    int x    = xw + lane;

    const __half2* tb  = g_pair + (size_t)b * THWc;
    const float* obase = off  + (size_t)b * 18 * HWc + (y0 << 9) + xw;
    const float* mbase = mask + (size_t)b * 9  * HWc + (y0 << 9) + xw;

    // Cooperative copy mapping (see R8-R10)
    int arr  = lane >> 4;
    int cc   = lane & 15;
    int coff = ((cc >> 3) << 9) + ((cc & 7) << 2);
    int moff = ((lane >> 3) << 9) + ((lane & 7) << 2);

    uint32_t warp_base = smem_u32(&slab[0][wrp][0]);
    uint32_t adst0 = warp_base + (uint32_t)lane * 16;
    uint32_t bdst0 = warp_base + 512 + (uint32_t)lane * 16;

    #pragma unroll
    for (int t = 0; t < NS; t++) {
        CP_ASYNC_16(adst0 + t * STAGE_BYTES, obase + (size_t)(2 * t + arr) * HWc + coff);
        if (lane < 16)
            CP_ASYNC_16(bdst0 + t * STAGE_BYTES, mbase + (size_t)t * HWc + moff);
        CP_COMMIT();
    }

    float acc0 = 0.0f, acc1 = 0.0f;
    float xf = (float)x;

    #pragma unroll
    for (int t = 0; t < 9; t++) {
        const int s = t % NS;

        CP_WAIT(NS - 1);
        __syncwarp();

        const float* f = &slab[s][wrp][0];
        float dy0 = f[lane],       dy1 = f[32 + lane];
        float dx0 = f[64 + lane],  dx1 = f[96 + lane];
        float m0  = f[128 + lane], m1  = f[160 + lane];

        int tn = t + NS;
        if (tn < 9) {
            CP_ASYNC_16(adst0 + s * STAGE_BYTES, obase + (size_t)(2 * tn + arr) * HWc + coff);
            if (lane < 16)
                CP_ASYNC_16(bdst0 + s * STAGE_BYTES, mbase + (size_t)tn * HWc + moff);
        }
        CP_COMMIT();

        float wt = __ldg(w9 + t);
        float ybase = (float)(y0 - 1 + t / 3);
        float xtap  = xf + (float)(t % 3 - 1);

        float sv;
        sv = bilin_pair(tb, ybase + 0.0f + dy0, xtap + dx0);
        acc0 = fmaf(sv, m0 * wt, acc0);
        sv = bilin_pair(tb, ybase + 1.0f + dy1, xtap + dx1);
        acc1 = fmaf(sv, m1 * wt, acc1);
    }

    float bv = __ldg(bias);
    float* optr = out + (size_t)b * HWc + (y0 << 9) + x;
    __stcs(optr,      acc0 + bv);       // write-once: evict-first
    __stcs(optr + Wc, acc1 + bv);
}

extern "C" void kernel_launch(void* const* d_in, const int* in_sizes, int n_in,
                              void* d_out, int out_size)
{
    const float* depth = (const float*)d_in[0];
    const float* mask  = (const float*)d_in[1];
    const float* off   = (const float*)d_in[2];
    const float* w9    = (const float*)d_in[3];
    const float* bias  = (const float*)d_in[4];
    float* out = (float*)d_out;

    int B = in_sizes[0] / HWc;

    prep_kernel<<<B * 512, 128>>>(depth);

    int blocks = B * 512;
    dcn_kernel<<<blocks, 256>>>(mask, off, w9, bias, out, B);
}